// round 15
// baseline (speedup 1.0000x reference)
#include <cuda_runtime.h>
#include <cuda_fp16.h>
#include <cstdint>
#include <math.h>

#define B_  2
#define T_  2048
#define D_  2048
#define H_  16
#define KV_ 4
#define HD_ 128
#define M_  (B_*T_)    // 4096
#define KVD_ (KV_*HD_) // 512
#define NQKV 3072      // packed Q(2048) + K(512) + V(512)

// ---------------- scratch ----------------------------------------------------
__device__ __half g_Xh[M_*D_];
__device__ __half g_W3h[NQKV*D_], g_W3l[NQKV*D_];   // lo only filled for Q rows
__device__ __half g_Woh[D_*D_],   g_Wol[D_*D_];
__device__ __half g_Qh[M_*D_];
__device__ __half g_Kh2[M_*KVD_];
__device__ __half g_Vth[M_*KVD_];                   // [(b*KV+g)*128+d][T]
__device__ __half g_Oh[M_*D_];

// ---------------- helpers -----------------------------------------------------
__device__ __forceinline__ void cvt2(float x, float y, uint32_t& h, uint32_t& l) {
    __half2 hh = __floats2half2_rn(x, y);
    float2 hf = __half22float2(hh);
    __half2 ll = __floats2half2_rn(x - hf.x, y - hf.y);
    h = *reinterpret_cast<uint32_t*>(&hh);
    l = *reinterpret_cast<uint32_t*>(&ll);
}
__device__ __forceinline__ uint32_t cvth(float x, float y) {
    __half2 hh = __floats2half2_rn(x, y);
    return *reinterpret_cast<uint32_t*>(&hh);
}
__device__ __forceinline__ void mma_f16(float* c, const uint32_t* a, const uint32_t* b) {
    asm volatile(
        "mma.sync.aligned.m16n8k16.row.col.f32.f16.f16.f32 "
        "{%0,%1,%2,%3}, {%4,%5,%6,%7}, {%8,%9}, {%0,%1,%2,%3};"
        : "+f"(c[0]), "+f"(c[1]), "+f"(c[2]), "+f"(c[3])
        : "r"(a[0]), "r"(a[1]), "r"(a[2]), "r"(a[3]), "r"(b[0]), "r"(b[1]));
}
__device__ __forceinline__ uint32_t s2u(const void* p) {
    uint32_t a;
    asm("{ .reg .u64 t; cvta.to.shared.u64 t, %1; cvt.u32.u64 %0, t; }" : "=r"(a) : "l"(p));
    return a;
}
#define LDSM4(r0, r1, r2, r3, addr) \
    asm volatile("ldmatrix.sync.aligned.m8n8.x4.shared.b16 {%0,%1,%2,%3}, [%4];" \
        : "=r"(r0), "=r"(r1), "=r"(r2), "=r"(r3) : "r"(addr))
#define CP16(dst, src) asm volatile("cp.async.cg.shared.global [%0], [%1], 16;" :: "r"(dst), "l"(src))
#define CPC   asm volatile("cp.async.commit_group;" ::: "memory")
#define CPW0  asm volatile("cp.async.wait_group 0;" ::: "memory")
#define CPW1  asm volatile("cp.async.wait_group 1;" ::: "memory")

// ---------------- fused split kernel (one launch for all 5 tensors) ----------
#define R_X   2097152                 // M*D/4
#define R_WQ  1048576                 // D*D/4
#define R_WKV 262144                  // KVD*D/4
#define SPLIT_TOTAL (R_X + R_WQ + 2*R_WKV + R_WQ)   // 4718592

__global__ void split_all(const float* __restrict__ x,  const float* __restrict__ wq,
                          const float* __restrict__ wk, const float* __restrict__ wv,
                          const float* __restrict__ wo,
                          __half* __restrict__ Xh,
                          __half* __restrict__ W3h, __half* __restrict__ W3l,
                          __half* __restrict__ Woh, __half* __restrict__ Wol)
{
    int i = blockIdx.x * blockDim.x + threadIdx.x;
    if (i < R_X) {
        float4 v = *(const float4*)(x + (size_t)i * 4);
        *(uint2*)(Xh + (size_t)i * 4) = make_uint2(cvth(v.x, v.y), cvth(v.z, v.w));
    } else if (i < R_X + R_WQ) {
        int j = i - R_X;
        float4 v = *(const float4*)(wq + (size_t)j * 4);
        uint32_t h0, l0, h1, l1;
        cvt2(v.x, v.y, h0, l0); cvt2(v.z, v.w, h1, l1);
        *(uint2*)(W3h + (size_t)j * 4) = make_uint2(h0, h1);
        *(uint2*)(W3l + (size_t)j * 4) = make_uint2(l0, l1);
    } else if (i < R_X + R_WQ + R_WKV) {
        int j = i - (R_X + R_WQ);
        float4 v = *(const float4*)(wk + (size_t)j * 4);
        *(uint2*)(W3h + (size_t)2048*2048 + (size_t)j * 4) = make_uint2(cvth(v.x, v.y), cvth(v.z, v.w));
    } else if (i < R_X + R_WQ + 2*R_WKV) {
        int j = i - (R_X + R_WQ + R_WKV);
        float4 v = *(const float4*)(wv + (size_t)j * 4);
        *(uint2*)(W3h + (size_t)2560*2048 + (size_t)j * 4) = make_uint2(cvth(v.x, v.y), cvth(v.z, v.w));
    } else {
        int j = i - (R_X + R_WQ + 2*R_WKV);
        float4 v = *(const float4*)(wo + (size_t)j * 4);
        uint32_t h0, l0, h1, l1;
        cvt2(v.x, v.y, h0, l0); cvt2(v.z, v.w, h1, l1);
        *(uint2*)(Woh + (size_t)j * 4) = make_uint2(h0, h1);
        *(uint2*)(Wol + (size_t)j * 4) = make_uint2(l0, l1);
    }
}

// ============================================================================
// Shared GEMM mainloop, templated on USE_BL (unchanged from round 14).
// ============================================================================
#define G2_BYTES 67584
#define TP 132

struct GemmCtx {
    float acc[4][4][4];
    int wm, wn, g, t;
};

template <bool USE_BL>
__device__ __forceinline__ void gemm_mainloop(
    const __half* __restrict__ Ah_g,
    const __half* __restrict__ Bh_g, const __half* __restrict__ Bl_g,
    int K, int bm, int bn, uint32_t* su, uint32_t sb, GemmCtx& cx)
{
    const int tid = threadIdx.x, lane = tid & 31, w = tid >> 5;
    cx.wm = (w & 1) * 64;
    cx.wn = (w >> 1) * 32;
    cx.g = lane >> 2; cx.t = lane & 3;

    const int matid = tid >> 6;
    const __half* gp = (matid == 0) ? Ah_g : (matid == 1) ? Bh_g : Bl_g;
    const int rowb = (matid == 0) ? bm : bn;
    const int t64 = tid & 63;
    const int rb0 = t64 >> 2, cc = t64 & 3;
    const uint32_t dstb = sb + matid*10240 + rb0*80 + cc*16;
    const __half* srcb = gp + (size_t)(rowb + rb0) * K + cc * 8;
    const bool loader = USE_BL ? (matid < 3) : (matid < 2);

    const int arow = cx.wm + ((lane >> 3) & 1) * 8 + (lane & 7);
    const uint32_t aBase = sb + arow * 80 + (lane >> 4) * 16;
    const int brow = cx.wn + (lane >> 4) * 8 + (lane & 7);
    const uint32_t bBase = sb + 10240 + brow * 80 + ((lane >> 3) & 1) * 16;

    #pragma unroll
    for (int mb = 0; mb < 4; mb++)
        #pragma unroll
        for (int nb = 0; nb < 4; nb++)
            #pragma unroll
            for (int i = 0; i < 4; i++) cx.acc[mb][nb][i] = 0.f;

    if (loader) {
        #pragma unroll
        for (int i = 0; i < 8; i++)
            CP16(dstb + i*1280, srcb + (size_t)(16*i) * K);
    }
    CPC;

    const int NT = K >> 5;
    for (int kt = 0; kt < NT; kt++) {
        const int stg = kt & 1;
        const uint32_t stgoff = stg * 30720;
        CPW0;
        __syncthreads();
        if (kt + 1 < NT && loader) {
            const __half* s = srcb + (kt + 1) * 32;
            const uint32_t d2 = dstb + (stg ^ 1) * 30720;
            #pragma unroll
            for (int i = 0; i < 8; i++)
                CP16(d2 + i*1280, s + (size_t)(16*i) * K);
        }
        CPC;

        #pragma unroll
        for (int ks = 0; ks < 2; ks++) {
            uint32_t ah[4][4], bh[4][2];
            #pragma unroll
            for (int mb = 0; mb < 4; mb++)
                LDSM4(ah[mb][0], ah[mb][1], ah[mb][2], ah[mb][3],
                      aBase + stgoff + mb*1280 + ks*32);
            #pragma unroll
            for (int nbp = 0; nbp < 2; nbp++)
                LDSM4(bh[2*nbp][0], bh[2*nbp][1], bh[2*nbp+1][0], bh[2*nbp+1][1],
                      bBase + stgoff + nbp*1280 + ks*32);
            if (USE_BL) {
                uint32_t bl[4][2];
                #pragma unroll
                for (int nbp = 0; nbp < 2; nbp++)
                    LDSM4(bl[2*nbp][0], bl[2*nbp][1], bl[2*nbp+1][0], bl[2*nbp+1][1],
                          bBase + stgoff + 10240 + nbp*1280 + ks*32);
                #pragma unroll
                for (int nb = 0; nb < 4; nb++)
                    #pragma unroll
                    for (int mb = 0; mb < 4; mb++) {
                        mma_f16(cx.acc[mb][nb], ah[mb], bh[nb]);
                        mma_f16(cx.acc[mb][nb], ah[mb], bl[nb]);
                    }
            } else {
                #pragma unroll
                for (int nb = 0; nb < 4; nb++)
                    #pragma unroll
                    for (int mb = 0; mb < 4; mb++)
                        mma_f16(cx.acc[mb][nb], ah[mb], bh[nb]);
            }
        }
    }
}

// ---- WO projection GEMM: plain f32 output (2-term) --------------------------
__global__ __launch_bounds__(256) void gemm_2t(
    const __half* __restrict__ Ah_g,
    const __half* __restrict__ Bh_g, const __half* __restrict__ Bl_g,
    float* __restrict__ C, int ldc, int K)
{
    extern __shared__ uint32_t su[];
    const uint32_t sb = s2u(su);
    const int bm = blockIdx.y * 128, bn = blockIdx.x * 128;
    GemmCtx cx;
    gemm_mainloop<true>(Ah_g, Bh_g, Bl_g, K, bm, bn, su, sb, cx);

    #pragma unroll
    for (int mb = 0; mb < 4; mb++) {
        int r0 = bm + cx.wm + mb * 16 + cx.g;
        #pragma unroll
        for (int nb = 0; nb < 4; nb++) {
            int ccn = bn + cx.wn + nb * 8 + 2 * cx.t;
            *(float2*)(C + (size_t)r0 * ldc + ccn)       = make_float2(cx.acc[mb][nb][0], cx.acc[mb][nb][1]);
            *(float2*)(C + (size_t)(r0 + 8) * ldc + ccn) = make_float2(cx.acc[mb][nb][2], cx.acc[mb][nb][3]);
        }
    }
}

// ---- fused QKV GEMM (unchanged from round 14) -------------------------------
__global__ __launch_bounds__(256) void gemm_qkv(
    const __half* __restrict__ Ah_g,
    const __half* __restrict__ Bh_g, const __half* __restrict__ Bl_g,
    __half* __restrict__ Qh, __half* __restrict__ Kh, __half* __restrict__ Vt)
{
    extern __shared__ uint32_t su[];
    const uint32_t sb = s2u(su);
    const int tid = threadIdx.x;
    const int bm = blockIdx.y * 128, bn = blockIdx.x * 128;
    GemmCtx cx;
    if (bn < 2048)
        gemm_mainloop<true>(Ah_g, Bh_g, Bl_g, D_, bm, bn, su, sb, cx);
    else
        gemm_mainloop<false>(Ah_g, Bh_g, Bl_g, D_, bm, bn, su, sb, cx);

    float* st = (float*)su;
    __syncthreads();
    #pragma unroll
    for (int mb = 0; mb < 4; mb++) {
        int r0 = cx.wm + mb * 16 + cx.g;
        #pragma unroll
        for (int nb = 0; nb < 4; nb++) {
            int ccn = cx.wn + nb * 8 + 2 * cx.t;
            *(float2*)(st + r0 * TP + ccn)       = make_float2(cx.acc[mb][nb][0], cx.acc[mb][nb][1]);
            *(float2*)(st + (r0 + 8) * TP + ccn) = make_float2(cx.acc[mb][nb][2], cx.acc[mb][nb][3]);
        }
    }
    __syncthreads();

    if (bn < 2048) {
        const int hh = bn >> 7;
        const float scale = 0.08838834764831845f;
        for (int p = tid; p < 8192; p += 256) {
            int r = p >> 6, j = p & 63;
            int m = bm + r, tpos = m & (T_ - 1);
            float inv = powf(10000.0f, -((float)(2 * j) / 128.0f));
            float s, c;
            sincosf((float)tpos * inv, &s, &c);
            float x1 = st[r * TP + j], x2 = st[r * TP + j + 64];
            __half* dst = Qh + (size_t)m * D_ + hh * HD_;
            dst[j]      = __float2half_rn((x1 * c - x2 * s) * scale);
            dst[j + 64] = __float2half_rn((x2 * c + x1 * s) * scale);
        }
    } else if (bn < 2560) {
        const int gg = (bn - 2048) >> 7;
        for (int p = tid; p < 8192; p += 256) {
            int r = p >> 6, j = p & 63;
            int m = bm + r, tpos = m & (T_ - 1);
            float inv = powf(10000.0f, -((float)(2 * j) / 128.0f));
            float s, c;
            sincosf((float)tpos * inv, &s, &c);
            float x1 = st[r * TP + j], x2 = st[r * TP + j + 64];
            __half* dst = Kh + (size_t)m * KVD_ + gg * HD_;
            dst[j]      = __float2half_rn(x1 * c - x2 * s);
            dst[j + 64] = __float2half_rn(x2 * c + x1 * s);
        }
    } else {
        const int d0 = bn - 2560;
        const int bb = bm >> 11;
        const int t0 = bm & (T_ - 1);
        for (int p = tid; p < 16384; p += 256) {
            int dl = p >> 7, tl = p & 127;
            float v = st[tl * TP + dl];
            Vt[(size_t)(bb * KVD_ + d0 + dl) * T_ + t0 + tl] = __float2half_rn(v);
        }
    }
}

// ============================================================================
// flash attention: KV tile 64, smem ~64 KB -> 3 CTAs/SM.
// Warp grid: QK 2(m)x4(s16); PV 2(m)x4(d32).
// ============================================================================
#define QH_OFF 0                  // 64 rows x 68 u32 (272 B)
#define KH_OFF 4352               // 64 rows x 68 u32
#define VH_OFF 8704               // 128 rows x 36 u32 (144 B)
#define PH_OFF 13312              // 64 rows x 36 u32
#define ST_OFF 15616              // stats
#define FA_SMEM_BYTES ((ST_OFF + 64*3 + 4*64*2) * 4)   // 65280 B

__global__ __launch_bounds__(256, 3) void flash_attn_h1(
    const __half* __restrict__ Qh_g,
    const __half* __restrict__ Kh_g,
    const __half* __restrict__ Vh_g,
    __half* __restrict__ Oh_g)
{
    extern __shared__ uint32_t su[];
    const uint32_t sb = s2u(su);
    uint32_t* Ph = su + PH_OFF;
    float* m_s  = (float*)(su + ST_OFF);
    float* l_s  = m_s + 64;
    float* rs_s = l_s + 64;
    float* pmax = rs_s + 64;
    float* psum = pmax + 4*64;

    const int tid = threadIdx.x, lane = tid & 31, w = tid >> 5;
    const int qt = blockIdx.x, h = blockIdx.y, b = blockIdx.z;
    const int gq = h >> 2;
    const int q0 = qt * 64;
    const int wm   = (w & 1) * 32;     // q rows
    const int wnq  = (w >> 1) * 16;    // QK: s cols
    const int wnp  = (w >> 1) * 32;    // PV: d cols
    const int g = lane >> 2, t = lane & 3;

    auto issueK = [&](int s0k) {
        #pragma unroll
        for (int i = 0; i < 4; i++) {
            int row = (tid >> 4) + i * 16, col = tid & 15;
            CP16(sb + (uint32_t)KH_OFF*4 + row*272 + col*16,
                 Kh_g + (size_t)(b*T_ + s0k + row) * KVD_ + gq*HD_ + col*8);
        }
    };
    auto issueV = [&](int s0v) {
        #pragma unroll
        for (int i = 0; i < 4; i++) {
            int row = (tid >> 3) + i * 32, col = tid & 7;
            CP16(sb + (uint32_t)VH_OFF*4 + row*144 + col*16,
                 Vh_g + ((size_t)(b*KV_ + gq)*HD_ + row) * T_ + s0v + col*8);
        }
    };

    // prologue: Q + K(0), then V(0)
    {
        #pragma unroll
        for (int i = 0; i < 4; i++) {
            int row = (tid >> 4) + i * 16, col = tid & 15;
            CP16(sb + (uint32_t)QH_OFF*4 + row*272 + col*16,
                 Qh_g + (size_t)(b*T_ + q0 + row) * D_ + h*HD_ + col*8);
        }
        issueK(0);
    }
    CPC;
    issueV(0);
    CPC;

    if (tid < 64) { m_s[tid] = -INFINITY; l_s[tid] = 0.f; }

    float acc[2][4][4];
    #pragma unroll
    for (int mb = 0; mb < 2; mb++)
        #pragma unroll
        for (int nb = 0; nb < 4; nb++)
            #pragma unroll
            for (int i = 0; i < 4; i++) acc[mb][nb][i] = 0.f;

    // ldmatrix bases
    const int arow = wm + ((lane >> 3) & 1) * 8 + (lane & 7);
    const uint32_t aBaseQ = sb + (uint32_t)QH_OFF*4 + arow * 272 + (lane >> 4) * 16;
    const uint32_t aBaseP = sb + (uint32_t)PH_OFF*4 + arow * 144 + (lane >> 4) * 16;
    const int browK = wnq + (lane >> 4) * 8 + (lane & 7);
    const uint32_t bBaseK = sb + (uint32_t)KH_OFF*4 + browK * 272 + ((lane >> 3) & 1) * 16;
    const int browV = wnp + (lane >> 4) * 8 + (lane & 7);
    const uint32_t bBaseV = sb + (uint32_t)VH_OFF*4 + browV * 144 + ((lane >> 3) & 1) * 16;

    for (int it = 0; it < 32; it++) {
        CPW1;
        __syncthreads();

        // ---- S = Q K^T (64 x 64) ----
        float sfr[2][2][4];
        #pragma unroll
        for (int mb = 0; mb < 2; mb++)
            #pragma unroll
            for (int nb = 0; nb < 2; nb++)
                #pragma unroll
                for (int i = 0; i < 4; i++) sfr[mb][nb][i] = 0.f;

        #pragma unroll
        for (int k16 = 0; k16 < 8; k16++) {
            uint32_t ah[2][4], bh[2][2];
            #pragma unroll
            for (int mb = 0; mb < 2; mb++)
                LDSM4(ah[mb][0], ah[mb][1], ah[mb][2], ah[mb][3],
                      aBaseQ + mb*16*272 + k16*32);
            LDSM4(bh[0][0], bh[0][1], bh[1][0], bh[1][1], bBaseK + k16*32);
            #pragma unroll
            for (int nb = 0; nb < 2; nb++)
                #pragma unroll
                for (int mb = 0; mb < 2; mb++)
                    mma_f16(sfr[mb][nb], ah[mb], bh[nb]);
        }

        // ---- row max (per-warp 16 s-cols, combine across 4 warp groups) ----
        #pragma unroll
        for (int mb = 0; mb < 2; mb++) {
            float m0 = fmaxf(fmaxf(sfr[mb][0][0], sfr[mb][0][1]),
                             fmaxf(sfr[mb][1][0], sfr[mb][1][1]));
            float m1 = fmaxf(fmaxf(sfr[mb][0][2], sfr[mb][0][3]),
                             fmaxf(sfr[mb][1][2], sfr[mb][1][3]));
            m0 = fmaxf(m0, __shfl_xor_sync(0xffffffffu, m0, 1));
            m0 = fmaxf(m0, __shfl_xor_sync(0xffffffffu, m0, 2));
            m1 = fmaxf(m1, __shfl_xor_sync(0xffffffffu, m1, 1));
            m1 = fmaxf(m1, __shfl_xor_sync(0xffffffffu, m1, 2));
            if (t == 0) {
                pmax[(w>>1)*64 + wm + mb*16 + g    ] = m0;
                pmax[(w>>1)*64 + wm + mb*16 + g + 8] = m1;
            }
        }
        __syncthreads();

        if (it + 1 < 32) issueK((it + 1) * 64);
        CPC;

        if (tid < 64) {
            int r = tid;
            float mt = fmaxf(fmaxf(pmax[r], pmax[64+r]), fmaxf(pmax[128+r], pmax[192+r]));
            float m_old = m_s[r];
            float m_new = fmaxf(m_old, mt);
            float rs = __expf(m_old - m_new);
            rs_s[r] = rs; m_s[r] = m_new; l_s[r] *= rs;
        }
        __syncthreads();

        // ---- exp, P->smem (fp16), partial sums; rescale acc ----
        float ps[2][2] = {{0.f,0.f},{0.f,0.f}};
        #pragma unroll
        for (int mb = 0; mb < 2; mb++) {
            int row0 = wm + mb*16 + g;
            float m0 = m_s[row0], m1 = m_s[row0 + 8];
            #pragma unroll
            for (int nb = 0; nb < 2; nb++) {
                int pp = (wnq >> 1) + nb*4 + t;
                float p0 = __expf(sfr[mb][nb][0] - m0);
                float p1 = __expf(sfr[mb][nb][1] - m0);
                float p2 = __expf(sfr[mb][nb][2] - m1);
                float p3 = __expf(sfr[mb][nb][3] - m1);
                ps[mb][0] += p0 + p1;
                ps[mb][1] += p2 + p3;
                Ph[row0*36 + pp]     = cvth(p0, p1);
                Ph[(row0+8)*36 + pp] = cvth(p2, p3);
            }
            ps[mb][0] += __shfl_xor_sync(0xffffffffu, ps[mb][0], 1);
            ps[mb][0] += __shfl_xor_sync(0xffffffffu, ps[mb][0], 2);
            ps[mb][1] += __shfl_xor_sync(0xffffffffu, ps[mb][1], 1);
            ps[mb][1] += __shfl_xor_sync(0xffffffffu, ps[mb][1], 2);
            if (t == 0) {
                psum[(w>>1)*64 + wm + mb*16 + g    ] = ps[mb][0];
                psum[(w>>1)*64 + wm + mb*16 + g + 8] = ps[mb][1];
            }
        }
        #pragma unroll
        for (int mb = 0; mb < 2; mb++) {
            int row0 = wm + mb*16 + g;
            float r0 = rs_s[row0], r1 = rs_s[row0 + 8];
            #pragma unroll
            for (int nb = 0; nb < 4; nb++) {
                acc[mb][nb][0] *= r0; acc[mb][nb][1] *= r0;
                acc[mb][nb][2] *= r1; acc[mb][nb][3] *= r1;
            }
        }
        if (it < 31) { CPW1; } else { CPW0; }
        __syncthreads();
        if (tid < 64)
            l_s[tid] += psum[tid] + psum[64+tid] + psum[128+tid] + psum[192+tid];

        // ---- O += P V (k = s = 64) ----
        #pragma unroll
        for (int k16 = 0; k16 < 4; k16++) {
            uint32_t ah[2][4], bh[4][2];
            #pragma unroll
            for (int mb = 0; mb < 2; mb++)
                LDSM4(ah[mb][0], ah[mb][1], ah[mb][2], ah[mb][3],
                      aBaseP + mb*16*144 + k16*32);
            #pragma unroll
            for (int nbp = 0; nbp < 2; nbp++)
                LDSM4(bh[2*nbp][0], bh[2*nbp][1], bh[2*nbp+1][0], bh[2*nbp+1][1],
                      bBaseV + nbp*16*144 + k16*32);
            #pragma unroll
            for (int nb = 0; nb < 4; nb++)
                #pragma unroll
                for (int mb = 0; mb < 2; mb++)
                    mma_f16(acc[mb][nb], ah[mb], bh[nb]);
        }
        __syncthreads();

        if (it + 1 < 32) issueV((it + 1) * 64);
        CPC;
    }

    // ---- epilogue ----
    #pragma unroll
    for (int mb = 0; mb < 2; mb++) {
        int row0 = wm + mb*16 + g;
        float inv0 = 1.0f / l_s[row0];
        float inv1 = 1.0f / l_s[row0 + 8];
        #pragma unroll
        for (int nb = 0; nb < 4; nb++) {
            int col = h*HD_ + wnp + nb*8 + 2*t;
            size_t o0 = (size_t)(b*T_ + q0 + row0) * D_ + col;
            size_t o1 = (size_t)(b*T_ + q0 + row0 + 8) * D_ + col;
            *(uint32_t*)(Oh_g + o0) = cvth(acc[mb][nb][0]*inv0, acc[mb][nb][1]*inv0);
            *(uint32_t*)(Oh_g + o1) = cvth(acc[mb][nb][2]*inv1, acc[mb][nb][3]*inv1);
        }
    }
}

// ---------------- launch ------------------------------------------------------
extern "C" void kernel_launch(void* const* d_in, const int* in_sizes, int n_in,
                              void* d_out, int out_size)
{
    const float* x  = (const float*)d_in[0];
    const float* wq = (const float*)d_in[1];
    const float* wk = (const float*)d_in[2];
    const float* wv = (const float*)d_in[3];
    const float* wo = (const float*)d_in[4];
    float* out = (float*)d_out;

    __half *pXh, *pW3h, *pW3l, *pWoh, *pWol;
    __half *pQh, *pKh, *pVth, *pOh;
    cudaGetSymbolAddress((void**)&pXh, g_Xh);
    cudaGetSymbolAddress((void**)&pW3h, g_W3h); cudaGetSymbolAddress((void**)&pW3l, g_W3l);
    cudaGetSymbolAddress((void**)&pWoh, g_Woh); cudaGetSymbolAddress((void**)&pWol, g_Wol);
    cudaGetSymbolAddress((void**)&pQh, g_Qh);
    cudaGetSymbolAddress((void**)&pKh, g_Kh2);
    cudaGetSymbolAddress((void**)&pVth, g_Vth);
    cudaGetSymbolAddress((void**)&pOh, g_Oh);

    cudaFuncSetAttribute(gemm_2t,  cudaFuncAttributeMaxDynamicSharedMemorySize, G2_BYTES);
    cudaFuncSetAttribute(gemm_qkv, cudaFuncAttributeMaxDynamicSharedMemorySize, G2_BYTES);
    cudaFuncSetAttribute(flash_attn_h1, cudaFuncAttributeMaxDynamicSharedMemorySize, FA_SMEM_BYTES);

    // one fused split kernel for all tensors
    split_all<<<SPLIT_TOTAL/256, 256>>>(x, wq, wk, wv, wo,
                                        pXh, pW3h, pW3l, pWoh, pWol);

    // fused QKV projection + RoPE + V-transpose
    gemm_qkv<<<dim3(NQKV/128, M_/128), 256, G2_BYTES>>>(pXh, pW3h, pW3l, pQh, pKh, pVth);

    flash_attn_h1<<<dim3(T_/64, H_, B_), 256, FA_SMEM_BYTES>>>(pQh, pKh, pVth, pOh);

    gemm_2t<<<dim3(D_/128, M_/128), 256, G2_BYTES>>>(pOh, pWoh, pWol, out, D_, D_);
}

// round 16
// speedup vs baseline: 1.0131x; 1.0131x over previous
#include <cuda_runtime.h>
#include <cuda_fp16.h>
#include <cstdint>
#include <math.h>

#define B_  2
#define T_  2048
#define D_  2048
#define H_  16
#define KV_ 4
#define HD_ 128
#define M_  (B_*T_)    // 4096
#define KVD_ (KV_*HD_) // 512
#define NQKV 3072      // packed Q(2048) + K(512) + V(512)

// ---------------- scratch ----------------------------------------------------
__device__ __half g_Xh[M_*D_];
__device__ __half g_W3h[NQKV*D_], g_W3l[NQKV*D_];   // lo only filled for Q rows
__device__ __half g_Woh[D_*D_],   g_Wol[D_*D_];
__device__ __half g_Qh[M_*D_];
__device__ __half g_Kh2[M_*KVD_];
__device__ __half g_Vth[M_*KVD_];                   // [(b*KV+g)*128+d][T]
__device__ __half g_Oh[M_*D_];

// ---------------- helpers -----------------------------------------------------
__device__ __forceinline__ void cvt2(float x, float y, uint32_t& h, uint32_t& l) {
    __half2 hh = __floats2half2_rn(x, y);
    float2 hf = __half22float2(hh);
    __half2 ll = __floats2half2_rn(x - hf.x, y - hf.y);
    h = *reinterpret_cast<uint32_t*>(&hh);
    l = *reinterpret_cast<uint32_t*>(&ll);
}
__device__ __forceinline__ uint32_t cvth(float x, float y) {
    __half2 hh = __floats2half2_rn(x, y);
    return *reinterpret_cast<uint32_t*>(&hh);
}
__device__ __forceinline__ void mma_f16(float* c, const uint32_t* a, const uint32_t* b) {
    asm volatile(
        "mma.sync.aligned.m16n8k16.row.col.f32.f16.f16.f32 "
        "{%0,%1,%2,%3}, {%4,%5,%6,%7}, {%8,%9}, {%0,%1,%2,%3};"
        : "+f"(c[0]), "+f"(c[1]), "+f"(c[2]), "+f"(c[3])
        : "r"(a[0]), "r"(a[1]), "r"(a[2]), "r"(a[3]), "r"(b[0]), "r"(b[1]));
}
__device__ __forceinline__ uint32_t s2u(const void* p) {
    uint32_t a;
    asm("{ .reg .u64 t; cvta.to.shared.u64 t, %1; cvt.u32.u64 %0, t; }" : "=r"(a) : "l"(p));
    return a;
}
#define LDSM4(r0, r1, r2, r3, addr) \
    asm volatile("ldmatrix.sync.aligned.m8n8.x4.shared.b16 {%0,%1,%2,%3}, [%4];" \
        : "=r"(r0), "=r"(r1), "=r"(r2), "=r"(r3) : "r"(addr))
#define CP16(dst, src) asm volatile("cp.async.cg.shared.global [%0], [%1], 16;" :: "r"(dst), "l"(src))
#define CPC   asm volatile("cp.async.commit_group;" ::: "memory")
#define CPW0  asm volatile("cp.async.wait_group 0;" ::: "memory")
#define CPW1  asm volatile("cp.async.wait_group 1;" ::: "memory")

// ---------------- fused split kernel ------------------------------------------
#define R_X   2097152
#define R_WQ  1048576
#define R_WKV 262144
#define SPLIT_TOTAL (R_X + R_WQ + 2*R_WKV + R_WQ)

__global__ void split_all(const float* __restrict__ x,  const float* __restrict__ wq,
                          const float* __restrict__ wk, const float* __restrict__ wv,
                          const float* __restrict__ wo,
                          __half* __restrict__ Xh,
                          __half* __restrict__ W3h, __half* __restrict__ W3l,
                          __half* __restrict__ Woh, __half* __restrict__ Wol)
{
    int i = blockIdx.x * blockDim.x + threadIdx.x;
    if (i < R_X) {
        float4 v = *(const float4*)(x + (size_t)i * 4);
        *(uint2*)(Xh + (size_t)i * 4) = make_uint2(cvth(v.x, v.y), cvth(v.z, v.w));
    } else if (i < R_X + R_WQ) {
        int j = i - R_X;
        float4 v = *(const float4*)(wq + (size_t)j * 4);
        uint32_t h0, l0, h1, l1;
        cvt2(v.x, v.y, h0, l0); cvt2(v.z, v.w, h1, l1);
        *(uint2*)(W3h + (size_t)j * 4) = make_uint2(h0, h1);
        *(uint2*)(W3l + (size_t)j * 4) = make_uint2(l0, l1);
    } else if (i < R_X + R_WQ + R_WKV) {
        int j = i - (R_X + R_WQ);
        float4 v = *(const float4*)(wk + (size_t)j * 4);
        *(uint2*)(W3h + (size_t)2048*2048 + (size_t)j * 4) = make_uint2(cvth(v.x, v.y), cvth(v.z, v.w));
    } else if (i < R_X + R_WQ + 2*R_WKV) {
        int j = i - (R_X + R_WQ + R_WKV);
        float4 v = *(const float4*)(wv + (size_t)j * 4);
        *(uint2*)(W3h + (size_t)2560*2048 + (size_t)j * 4) = make_uint2(cvth(v.x, v.y), cvth(v.z, v.w));
    } else {
        int j = i - (R_X + R_WQ + 2*R_WKV);
        float4 v = *(const float4*)(wo + (size_t)j * 4);
        uint32_t h0, l0, h1, l1;
        cvt2(v.x, v.y, h0, l0); cvt2(v.z, v.w, h1, l1);
        *(uint2*)(Woh + (size_t)j * 4) = make_uint2(h0, h1);
        *(uint2*)(Wol + (size_t)j * 4) = make_uint2(l0, l1);
    }
}

// ============================================================================
// Shared GEMM mainloop: 3-stage cp.async pipeline, templated on USE_BL.
// Stage = 3 matrices x 10240 B = 30720 B; 3 stages = 92160 B.
// ============================================================================
#define STAGE_B  30720
#define G2_BYTES 92160
#define TP 132

struct GemmCtx {
    float acc[4][4][4];
    int wm, wn, g, t;
};

template <bool USE_BL>
__device__ __forceinline__ void gemm_mainloop(
    const __half* __restrict__ Ah_g,
    const __half* __restrict__ Bh_g, const __half* __restrict__ Bl_g,
    int K, int bm, int bn, uint32_t* su, uint32_t sb, GemmCtx& cx)
{
    const int tid = threadIdx.x, lane = tid & 31, w = tid >> 5;
    cx.wm = (w & 1) * 64;
    cx.wn = (w >> 1) * 32;
    cx.g = lane >> 2; cx.t = lane & 3;

    const int matid = tid >> 6;
    const __half* gp = (matid == 0) ? Ah_g : (matid == 1) ? Bh_g : Bl_g;
    const int rowb = (matid == 0) ? bm : bn;
    const int t64 = tid & 63;
    const int rb0 = t64 >> 2, cc = t64 & 3;
    const uint32_t dstb = sb + matid*10240 + rb0*80 + cc*16;
    const __half* srcb = gp + (size_t)(rowb + rb0) * K + cc * 8;
    const bool loader = USE_BL ? (matid < 3) : (matid < 2);

    const int arow = cx.wm + ((lane >> 3) & 1) * 8 + (lane & 7);
    const uint32_t aBase = sb + arow * 80 + (lane >> 4) * 16;
    const int brow = cx.wn + (lane >> 4) * 8 + (lane & 7);
    const uint32_t bBase = sb + 10240 + brow * 80 + ((lane >> 3) & 1) * 16;

    #pragma unroll
    for (int mb = 0; mb < 4; mb++)
        #pragma unroll
        for (int nb = 0; nb < 4; nb++)
            #pragma unroll
            for (int i = 0; i < 4; i++) cx.acc[mb][nb][i] = 0.f;

    const int NT = K >> 5;

    // prologue: stages 0 and 1
    if (loader) {
        #pragma unroll
        for (int i = 0; i < 8; i++)
            CP16(dstb + i*1280, srcb + (size_t)(16*i) * K);
    }
    CPC;
    if (loader && NT > 1) {
        const __half* s = srcb + 32;
        #pragma unroll
        for (int i = 0; i < 8; i++)
            CP16(dstb + STAGE_B + i*1280, s + (size_t)(16*i) * K);
    }
    CPC;

    uint32_t sc = 0, sp = 2 * STAGE_B;   // compute / prefetch stage byte offsets
    for (int kt = 0; kt < NT; kt++) {
        CPW1;                            // stage kt resident
        __syncthreads();                 // stage (kt+2)%3 free for overwrite
        if (kt + 2 < NT && loader) {
            const __half* s = srcb + (kt + 2) * 32;
            const uint32_t d2 = dstb + sp;
            #pragma unroll
            for (int i = 0; i < 8; i++)
                CP16(d2 + i*1280, s + (size_t)(16*i) * K);
        }
        CPC;                             // unconditional: uniform group cadence

        #pragma unroll
        for (int ks = 0; ks < 2; ks++) {
            uint32_t ah[4][4], bh[4][2];
            #pragma unroll
            for (int mb = 0; mb < 4; mb++)
                LDSM4(ah[mb][0], ah[mb][1], ah[mb][2], ah[mb][3],
                      aBase + sc + mb*1280 + ks*32);
            #pragma unroll
            for (int nbp = 0; nbp < 2; nbp++)
                LDSM4(bh[2*nbp][0], bh[2*nbp][1], bh[2*nbp+1][0], bh[2*nbp+1][1],
                      bBase + sc + nbp*1280 + ks*32);
            if (USE_BL) {
                uint32_t bl[4][2];
                #pragma unroll
                for (int nbp = 0; nbp < 2; nbp++)
                    LDSM4(bl[2*nbp][0], bl[2*nbp][1], bl[2*nbp+1][0], bl[2*nbp+1][1],
                          bBase + sc + 10240 + nbp*1280 + ks*32);
                #pragma unroll
                for (int nb = 0; nb < 4; nb++)
                    #pragma unroll
                    for (int mb = 0; mb < 4; mb++) {
                        mma_f16(cx.acc[mb][nb], ah[mb], bh[nb]);
                        mma_f16(cx.acc[mb][nb], ah[mb], bl[nb]);
                    }
            } else {
                #pragma unroll
                for (int nb = 0; nb < 4; nb++)
                    #pragma unroll
                    for (int mb = 0; mb < 4; mb++)
                        mma_f16(cx.acc[mb][nb], ah[mb], bh[nb]);
            }
        }
        sc += STAGE_B; if (sc == 3*STAGE_B) sc = 0;
        sp += STAGE_B; if (sp == 3*STAGE_B) sp = 0;
    }
}

// ---- WO projection GEMM: plain f32 output (2-term) --------------------------
__global__ __launch_bounds__(256) void gemm_2t(
    const __half* __restrict__ Ah_g,
    const __half* __restrict__ Bh_g, const __half* __restrict__ Bl_g,
    float* __restrict__ C, int ldc, int K)
{
    extern __shared__ uint32_t su[];
    const uint32_t sb = s2u(su);
    const int bm = blockIdx.y * 128, bn = blockIdx.x * 128;
    GemmCtx cx;
    gemm_mainloop<true>(Ah_g, Bh_g, Bl_g, K, bm, bn, su, sb, cx);

    #pragma unroll
    for (int mb = 0; mb < 4; mb++) {
        int r0 = bm + cx.wm + mb * 16 + cx.g;
        #pragma unroll
        for (int nb = 0; nb < 4; nb++) {
            int ccn = bn + cx.wn + nb * 8 + 2 * cx.t;
            *(float2*)(C + (size_t)r0 * ldc + ccn)       = make_float2(cx.acc[mb][nb][0], cx.acc[mb][nb][1]);
            *(float2*)(C + (size_t)(r0 + 8) * ldc + ccn) = make_float2(cx.acc[mb][nb][2], cx.acc[mb][nb][3]);
        }
    }
}

// ---- fused QKV GEMM: 2-term Q cols / 1-term K,V cols; fused epilogue --------
__global__ __launch_bounds__(256) void gemm_qkv(
    const __half* __restrict__ Ah_g,
    const __half* __restrict__ Bh_g, const __half* __restrict__ Bl_g,
    __half* __restrict__ Qh, __half* __restrict__ Kh, __half* __restrict__ Vt)
{
    extern __shared__ uint32_t su[];
    const uint32_t sb = s2u(su);
    const int tid = threadIdx.x;
    const int bm = blockIdx.y * 128, bn = blockIdx.x * 128;
    GemmCtx cx;
    if (bn < 2048)
        gemm_mainloop<true>(Ah_g, Bh_g, Bl_g, D_, bm, bn, su, sb, cx);
    else
        gemm_mainloop<false>(Ah_g, Bh_g, Bl_g, D_, bm, bn, su, sb, cx);

    float* st = (float*)su;
    __syncthreads();
    #pragma unroll
    for (int mb = 0; mb < 4; mb++) {
        int r0 = cx.wm + mb * 16 + cx.g;
        #pragma unroll
        for (int nb = 0; nb < 4; nb++) {
            int ccn = cx.wn + nb * 8 + 2 * cx.t;
            *(float2*)(st + r0 * TP + ccn)       = make_float2(cx.acc[mb][nb][0], cx.acc[mb][nb][1]);
            *(float2*)(st + (r0 + 8) * TP + ccn) = make_float2(cx.acc[mb][nb][2], cx.acc[mb][nb][3]);
        }
    }
    __syncthreads();

    if (bn < 2048) {
        const int hh = bn >> 7;
        const float scale = 0.08838834764831845f;
        for (int p = tid; p < 8192; p += 256) {
            int r = p >> 6, j = p & 63;
            int m = bm + r, tpos = m & (T_ - 1);
            float inv = powf(10000.0f, -((float)(2 * j) / 128.0f));
            float s, c;
            sincosf((float)tpos * inv, &s, &c);
            float x1 = st[r * TP + j], x2 = st[r * TP + j + 64];
            __half* dst = Qh + (size_t)m * D_ + hh * HD_;
            dst[j]      = __float2half_rn((x1 * c - x2 * s) * scale);
            dst[j + 64] = __float2half_rn((x2 * c + x1 * s) * scale);
        }
    } else if (bn < 2560) {
        const int gg = (bn - 2048) >> 7;
        for (int p = tid; p < 8192; p += 256) {
            int r = p >> 6, j = p & 63;
            int m = bm + r, tpos = m & (T_ - 1);
            float inv = powf(10000.0f, -((float)(2 * j) / 128.0f));
            float s, c;
            sincosf((float)tpos * inv, &s, &c);
            float x1 = st[r * TP + j], x2 = st[r * TP + j + 64];
            __half* dst = Kh + (size_t)m * KVD_ + gg * HD_;
            dst[j]      = __float2half_rn(x1 * c - x2 * s);
            dst[j + 64] = __float2half_rn(x2 * c + x1 * s);
        }
    } else {
        const int d0 = bn - 2560;
        const int bb = bm >> 11;
        const int t0 = bm & (T_ - 1);
        for (int p = tid; p < 16384; p += 256) {
            int dl = p >> 7, tl = p & 127;
            float v = st[tl * TP + dl];
            Vt[(size_t)(bb * KVD_ + d0 + dl) * T_ + t0 + tl] = __float2half_rn(v);
        }
    }
}

// ============================================================================
// flash attention: KV tile 128 (round-14 config, reverted).
// ============================================================================
#define AP 68
#define QH_OFF 0
#define KH_OFF (64*AP)
#define VH_OFF (192*AP)
#define PH_OFF (320*AP)
#define ST_OFF (384*AP)
#define FA_SMEM_BYTES ((ST_OFF + 64*3 + 4*64*2) * 4)   // ~107 KB

__global__ __launch_bounds__(256) void flash_attn_h1(
    const __half* __restrict__ Qh_g,
    const __half* __restrict__ Kh_g,
    const __half* __restrict__ Vh_g,
    __half* __restrict__ Oh_g)
{
    extern __shared__ uint32_t su[];
    const uint32_t sb = s2u(su);
    uint32_t* Ph = su + PH_OFF;
    float* m_s  = (float*)(su + ST_OFF);
    float* l_s  = m_s + 64;
    float* rs_s = l_s + 64;
    float* pmax = rs_s + 64;
    float* psum = pmax + 4*64;

    const int tid = threadIdx.x, lane = tid & 31, w = tid >> 5;
    const int qt = blockIdx.x, h = blockIdx.y, b = blockIdx.z;
    const int gq = h >> 2;
    const int q0 = qt * 64;
    const int wm = (w & 1) * 32;
    const int wn = (w >> 1) * 32;
    const int g = lane >> 2, t = lane & 3;

    const int vr = tid >> 4, vc = tid & 15;

    auto issueK = [&](int s0k) {
        const __half* src = Kh_g + (size_t)(b*T_ + s0k + vr) * KVD_ + gq*HD_ + vc*8;
        uint32_t dst = sb + (uint32_t)KH_OFF*4 + vr*272 + vc*16;
        #pragma unroll
        for (int i = 0; i < 8; i++)
            CP16(dst + i*16*272, src + (size_t)(16*i) * KVD_);
    };
    auto issueV = [&](int s0v) {
        const __half* src = Vh_g + ((size_t)(b*KV_ + gq)*HD_ + vr) * T_ + s0v + vc*8;
        uint32_t dst = sb + (uint32_t)VH_OFF*4 + vr*272 + vc*16;
        #pragma unroll
        for (int i = 0; i < 8; i++)
            CP16(dst + i*16*272, src + (size_t)(16*i) * T_);
    };

    {
        const __half* src = Qh_g + (size_t)(b*T_ + q0 + vr) * D_ + h*HD_ + vc*8;
        uint32_t dst = sb + (uint32_t)QH_OFF*4 + vr*272 + vc*16;
        #pragma unroll
        for (int i = 0; i < 4; i++)
            CP16(dst + i*16*272, src + (size_t)(16*i) * D_);
        issueK(0);
    }
    CPC;
    issueV(0);
    CPC;

    if (tid < 64) { m_s[tid] = -INFINITY; l_s[tid] = 0.f; }

    float acc[2][4][4];
    #pragma unroll
    for (int mb = 0; mb < 2; mb++)
        #pragma unroll
        for (int nb = 0; nb < 4; nb++)
            #pragma unroll
            for (int i = 0; i < 4; i++) acc[mb][nb][i] = 0.f;

    const int arow = wm + ((lane >> 3) & 1) * 8 + (lane & 7);
    const uint32_t aBase = sb + arow * 272 + (lane >> 4) * 16;
    const int brow = wn + (lane >> 4) * 8 + (lane & 7);
    const uint32_t bBase = sb + brow * 272 + ((lane >> 3) & 1) * 16;

    for (int it = 0; it < 16; it++) {
        CPW1;
        __syncthreads();

        float sfr[2][4][4];
        #pragma unroll
        for (int mb = 0; mb < 2; mb++)
            #pragma unroll
            for (int nb = 0; nb < 4; nb++)
                #pragma unroll
                for (int i = 0; i < 4; i++) sfr[mb][nb][i] = 0.f;

        #pragma unroll
        for (int k16 = 0; k16 < 8; k16++) {
            uint32_t ah[2][4], bh[4][2];
            #pragma unroll
            for (int mb = 0; mb < 2; mb++)
                LDSM4(ah[mb][0], ah[mb][1], ah[mb][2], ah[mb][3],
                      aBase + QH_OFF*4 + mb*16*272 + k16*32);
            #pragma unroll
            for (int nbp = 0; nbp < 2; nbp++)
                LDSM4(bh[2*nbp][0], bh[2*nbp][1], bh[2*nbp+1][0], bh[2*nbp+1][1],
                      bBase + KH_OFF*4 + nbp*16*272 + k16*32);
            #pragma unroll
            for (int nb = 0; nb < 4; nb++)
                #pragma unroll
                for (int mb = 0; mb < 2; mb++)
                    mma_f16(sfr[mb][nb], ah[mb], bh[nb]);
        }

        #pragma unroll
        for (int mb = 0; mb < 2; mb++) {
            float m0 = -INFINITY, m1 = -INFINITY;
            #pragma unroll
            for (int nb = 0; nb < 4; nb++) {
                m0 = fmaxf(m0, fmaxf(sfr[mb][nb][0], sfr[mb][nb][1]));
                m1 = fmaxf(m1, fmaxf(sfr[mb][nb][2], sfr[mb][nb][3]));
            }
            m0 = fmaxf(m0, __shfl_xor_sync(0xffffffffu, m0, 1));
            m0 = fmaxf(m0, __shfl_xor_sync(0xffffffffu, m0, 2));
            m1 = fmaxf(m1, __shfl_xor_sync(0xffffffffu, m1, 1));
            m1 = fmaxf(m1, __shfl_xor_sync(0xffffffffu, m1, 2));
            if (t == 0) {
                pmax[(w>>1)*64 + wm + mb*16 + g    ] = m0;
                pmax[(w>>1)*64 + wm + mb*16 + g + 8] = m1;
            }
        }
        __syncthreads();

        if (it + 1 < 16) issueK((it + 1) * 128);
        CPC;

        if (tid < 64) {
            int r = tid;
            float mt = fmaxf(fmaxf(pmax[r], pmax[64+r]), fmaxf(pmax[128+r], pmax[192+r]));
            float m_old = m_s[r];
            float m_new = fmaxf(m_old, mt);
            float rs = __expf(m_old - m_new);
            rs_s[r] = rs; m_s[r] = m_new; l_s[r] *= rs;
        }
        __syncthreads();

        float ps[2][2] = {{0.f,0.f},{0.f,0.f}};
        #pragma unroll
        for (int mb = 0; mb < 2; mb++) {
            int row0 = wm + mb*16 + g;
            float m0 = m_s[row0], m1 = m_s[row0 + 8];
            #pragma unroll
            for (int nb = 0; nb < 4; nb++) {
                int pp = (wn >> 1) + nb*4 + t;
                float p0 = __expf(sfr[mb][nb][0] - m0);
                float p1 = __expf(sfr[mb][nb][1] - m0);
                float p2 = __expf(sfr[mb][nb][2] - m1);
                float p3 = __expf(sfr[mb][nb][3] - m1);
                ps[mb][0] += p0 + p1;
                ps[mb][1] += p2 + p3;
                Ph[row0*AP + pp]     = cvth(p0, p1);
                Ph[(row0+8)*AP + pp] = cvth(p2, p3);
            }
            ps[mb][0] += __shfl_xor_sync(0xffffffffu, ps[mb][0], 1);
            ps[mb][0] += __shfl_xor_sync(0xffffffffu, ps[mb][0], 2);
            ps[mb][1] += __shfl_xor_sync(0xffffffffu, ps[mb][1], 1);
            ps[mb][1] += __shfl_xor_sync(0xffffffffu, ps[mb][1], 2);
            if (t == 0) {
                psum[(w>>1)*64 + wm + mb*16 + g    ] = ps[mb][0];
                psum[(w>>1)*64 + wm + mb*16 + g + 8] = ps[mb][1];
            }
        }
        #pragma unroll
        for (int mb = 0; mb < 2; mb++) {
            int row0 = wm + mb*16 + g;
            float r0 = rs_s[row0], r1 = rs_s[row0 + 8];
            #pragma unroll
            for (int nb = 0; nb < 4; nb++) {
                acc[mb][nb][0] *= r0; acc[mb][nb][1] *= r0;
                acc[mb][nb][2] *= r1; acc[mb][nb][3] *= r1;
            }
        }
        if (it < 15) { CPW1; } else { CPW0; }
        __syncthreads();
        if (tid < 64)
            l_s[tid] += psum[tid] + psum[64+tid] + psum[128+tid] + psum[192+tid];

        #pragma unroll
        for (int k16 = 0; k16 < 8; k16++) {
            uint32_t ah[2][4], bh[4][2];
            #pragma unroll
            for (int mb = 0; mb < 2; mb++)
                LDSM4(ah[mb][0], ah[mb][1], ah[mb][2], ah[mb][3],
                      aBase + PH_OFF*4 + mb*16*272 + k16*32);
            #pragma unroll
            for (int nbp = 0; nbp < 2; nbp++)
                LDSM4(bh[2*nbp][0], bh[2*nbp][1], bh[2*nbp+1][0], bh[2*nbp+1][1],
                      bBase + VH_OFF*4 + nbp*16*272 + k16*32);
            #pragma unroll
            for (int nb = 0; nb < 4; nb++)
                #pragma unroll
                for (int mb = 0; mb < 2; mb++)
                    mma_f16(acc[mb][nb], ah[mb], bh[nb]);
        }
        __syncthreads();

        if (it + 1 < 16) issueV((it + 1) * 128);
        CPC;
    }

    #pragma unroll
    for (int mb = 0; mb < 2; mb++) {
        int row0 = wm + mb*16 + g;
        float inv0 = 1.0f / l_s[row0];
        float inv1 = 1.0f / l_s[row0 + 8];
        #pragma unroll
        for (int nb = 0; nb < 4; nb++) {
            int col = h*HD_ + wn + nb*8 + 2*t;
            size_t o0 = (size_t)(b*T_ + q0 + row0) * D_ + col;
            size_t o1 = (size_t)(b*T_ + q0 + row0 + 8) * D_ + col;
            *(uint32_t*)(Oh_g + o0) = cvth(acc[mb][nb][0]*inv0, acc[mb][nb][1]*inv0);
            *(uint32_t*)(Oh_g + o1) = cvth(acc[mb][nb][2]*inv1, acc[mb][nb][3]*inv1);
        }
    }
}

// ---------------- launch ------------------------------------------------------
extern "C" void kernel_launch(void* const* d_in, const int* in_sizes, int n_in,
                              void* d_out, int out_size)
{
    const float* x  = (const float*)d_in[0];
    const float* wq = (const float*)d_in[1];
    const float* wk = (const float*)d_in[2];
    const float* wv = (const float*)d_in[3];
    const float* wo = (const float*)d_in[4];
    float* out = (float*)d_out;

    __half *pXh, *pW3h, *pW3l, *pWoh, *pWol;
    __half *pQh, *pKh, *pVth, *pOh;
    cudaGetSymbolAddress((void**)&pXh, g_Xh);
    cudaGetSymbolAddress((void**)&pW3h, g_W3h); cudaGetSymbolAddress((void**)&pW3l, g_W3l);
    cudaGetSymbolAddress((void**)&pWoh, g_Woh); cudaGetSymbolAddress((void**)&pWol, g_Wol);
    cudaGetSymbolAddress((void**)&pQh, g_Qh);
    cudaGetSymbolAddress((void**)&pKh, g_Kh2);
    cudaGetSymbolAddress((void**)&pVth, g_Vth);
    cudaGetSymbolAddress((void**)&pOh, g_Oh);

    cudaFuncSetAttribute(gemm_2t,  cudaFuncAttributeMaxDynamicSharedMemorySize, G2_BYTES);
    cudaFuncSetAttribute(gemm_qkv, cudaFuncAttributeMaxDynamicSharedMemorySize, G2_BYTES);
    cudaFuncSetAttribute(flash_attn_h1, cudaFuncAttributeMaxDynamicSharedMemorySize, FA_SMEM_BYTES);

    split_all<<<SPLIT_TOTAL/256, 256>>>(x, wq, wk, wv, wo,
                                        pXh, pW3h, pW3l, pWoh, pWol);

    gemm_qkv<<<dim3(NQKV/128, M_/128), 256, G2_BYTES>>>(pXh, pW3h, pW3l, pQh, pKh, pVth);

    flash_attn_h1<<<dim3(T_/64, H_, B_), 256, FA_SMEM_BYTES>>>(pQh, pKh, pVth, pOh);

    gemm_2t<<<dim3(D_/128, M_/128), 256, G2_BYTES>>>(pOh, pWoh, pWol, out, D_, D_);
}

// round 17
// speedup vs baseline: 1.0357x; 1.0223x over previous
#include <cuda_runtime.h>
#include <cuda_fp16.h>
#include <cstdint>
#include <math.h>

#define B_  2
#define T_  2048
#define D_  2048
#define H_  16
#define KV_ 4
#define HD_ 128
#define M_  (B_*T_)    // 4096
#define KVD_ (KV_*HD_) // 512
#define NQKV 3072      // packed Q(2048) + K(512) + V(512)

// ---------------- scratch ----------------------------------------------------
__device__ __half g_Xh[M_*D_];
__device__ __half g_W3h[NQKV*D_], g_W3l[NQKV*D_];   // lo only filled for Q rows
__device__ __half g_Woh[D_*D_],   g_Wol[D_*D_];
__device__ __half g_Qh[M_*D_];
__device__ __half g_Kh2[M_*KVD_];
__device__ __half g_Vth[M_*KVD_];                   // [(b*KV+g)*128+d][T]
__device__ __half g_Oh[M_*D_];

// ---------------- helpers -----------------------------------------------------
__device__ __forceinline__ void cvt2(float x, float y, uint32_t& h, uint32_t& l) {
    __half2 hh = __floats2half2_rn(x, y);
    float2 hf = __half22float2(hh);
    __half2 ll = __floats2half2_rn(x - hf.x, y - hf.y);
    h = *reinterpret_cast<uint32_t*>(&hh);
    l = *reinterpret_cast<uint32_t*>(&ll);
}
__device__ __forceinline__ uint32_t cvth(float x, float y) {
    __half2 hh = __floats2half2_rn(x, y);
    return *reinterpret_cast<uint32_t*>(&hh);
}
__device__ __forceinline__ void mma_f16(float* c, const uint32_t* a, const uint32_t* b) {
    asm volatile(
        "mma.sync.aligned.m16n8k16.row.col.f32.f16.f16.f32 "
        "{%0,%1,%2,%3}, {%4,%5,%6,%7}, {%8,%9}, {%0,%1,%2,%3};"
        : "+f"(c[0]), "+f"(c[1]), "+f"(c[2]), "+f"(c[3])
        : "r"(a[0]), "r"(a[1]), "r"(a[2]), "r"(a[3]), "r"(b[0]), "r"(b[1]));
}
__device__ __forceinline__ uint32_t s2u(const void* p) {
    uint32_t a;
    asm("{ .reg .u64 t; cvta.to.shared.u64 t, %1; cvt.u32.u64 %0, t; }" : "=r"(a) : "l"(p));
    return a;
}
#define LDSM4(r0, r1, r2, r3, addr) \
    asm volatile("ldmatrix.sync.aligned.m8n8.x4.shared.b16 {%0,%1,%2,%3}, [%4];" \
        : "=r"(r0), "=r"(r1), "=r"(r2), "=r"(r3) : "r"(addr))
#define CP16(dst, src) asm volatile("cp.async.cg.shared.global [%0], [%1], 16;" :: "r"(dst), "l"(src))
#define CPC   asm volatile("cp.async.commit_group;" ::: "memory")
#define CPW0  asm volatile("cp.async.wait_group 0;" ::: "memory")
#define CPW1  asm volatile("cp.async.wait_group 1;" ::: "memory")

// ---------------- fused split kernel ------------------------------------------
#define R_X   2097152
#define R_WQ  1048576
#define R_WKV 262144
#define SPLIT_TOTAL (R_X + R_WQ + 2*R_WKV + R_WQ)

__global__ void split_all(const float* __restrict__ x,  const float* __restrict__ wq,
                          const float* __restrict__ wk, const float* __restrict__ wv,
                          const float* __restrict__ wo,
                          __half* __restrict__ Xh,
                          __half* __restrict__ W3h, __half* __restrict__ W3l,
                          __half* __restrict__ Woh, __half* __restrict__ Wol)
{
    int i = blockIdx.x * blockDim.x + threadIdx.x;
    if (i < R_X) {
        float4 v = *(const float4*)(x + (size_t)i * 4);
        *(uint2*)(Xh + (size_t)i * 4) = make_uint2(cvth(v.x, v.y), cvth(v.z, v.w));
    } else if (i < R_X + R_WQ) {
        int j = i - R_X;
        float4 v = *(const float4*)(wq + (size_t)j * 4);
        uint32_t h0, l0, h1, l1;
        cvt2(v.x, v.y, h0, l0); cvt2(v.z, v.w, h1, l1);
        *(uint2*)(W3h + (size_t)j * 4) = make_uint2(h0, h1);
        *(uint2*)(W3l + (size_t)j * 4) = make_uint2(l0, l1);
    } else if (i < R_X + R_WQ + R_WKV) {
        int j = i - (R_X + R_WQ);
        float4 v = *(const float4*)(wk + (size_t)j * 4);
        *(uint2*)(W3h + (size_t)2048*2048 + (size_t)j * 4) = make_uint2(cvth(v.x, v.y), cvth(v.z, v.w));
    } else if (i < R_X + R_WQ + 2*R_WKV) {
        int j = i - (R_X + R_WQ + R_WKV);
        float4 v = *(const float4*)(wv + (size_t)j * 4);
        *(uint2*)(W3h + (size_t)2560*2048 + (size_t)j * 4) = make_uint2(cvth(v.x, v.y), cvth(v.z, v.w));
    } else {
        int j = i - (R_X + R_WQ + 2*R_WKV);
        float4 v = *(const float4*)(wo + (size_t)j * 4);
        uint32_t h0, l0, h1, l1;
        cvt2(v.x, v.y, h0, l0); cvt2(v.z, v.w, h1, l1);
        *(uint2*)(Woh + (size_t)j * 4) = make_uint2(h0, h1);
        *(uint2*)(Wol + (size_t)j * 4) = make_uint2(l0, l1);
    }
}

// ============================================================================
// Shared GEMM mainloop: 2-stage cp.async pipeline (round-14 proven config),
// templated on USE_BL.
// ============================================================================
#define G2_BYTES 67584
#define TP 132

struct GemmCtx {
    float acc[4][4][4];
    int wm, wn, g, t;
};

template <bool USE_BL>
__device__ __forceinline__ void gemm_mainloop(
    const __half* __restrict__ Ah_g,
    const __half* __restrict__ Bh_g, const __half* __restrict__ Bl_g,
    int K, int bm, int bn, uint32_t* su, uint32_t sb, GemmCtx& cx)
{
    const int tid = threadIdx.x, lane = tid & 31, w = tid >> 5;
    cx.wm = (w & 1) * 64;
    cx.wn = (w >> 1) * 32;
    cx.g = lane >> 2; cx.t = lane & 3;

    const int matid = tid >> 6;
    const __half* gp = (matid == 0) ? Ah_g : (matid == 1) ? Bh_g : Bl_g;
    const int rowb = (matid == 0) ? bm : bn;
    const int t64 = tid & 63;
    const int rb0 = t64 >> 2, cc = t64 & 3;
    const uint32_t dstb = sb + matid*10240 + rb0*80 + cc*16;
    const __half* srcb = gp + (size_t)(rowb + rb0) * K + cc * 8;
    const bool loader = USE_BL ? (matid < 3) : (matid < 2);

    const int arow = cx.wm + ((lane >> 3) & 1) * 8 + (lane & 7);
    const uint32_t aBase = sb + arow * 80 + (lane >> 4) * 16;
    const int brow = cx.wn + (lane >> 4) * 8 + (lane & 7);
    const uint32_t bBase = sb + 10240 + brow * 80 + ((lane >> 3) & 1) * 16;

    #pragma unroll
    for (int mb = 0; mb < 4; mb++)
        #pragma unroll
        for (int nb = 0; nb < 4; nb++)
            #pragma unroll
            for (int i = 0; i < 4; i++) cx.acc[mb][nb][i] = 0.f;

    if (loader) {
        #pragma unroll
        for (int i = 0; i < 8; i++)
            CP16(dstb + i*1280, srcb + (size_t)(16*i) * K);
    }
    CPC;

    const int NT = K >> 5;
    for (int kt = 0; kt < NT; kt++) {
        const int stg = kt & 1;
        const uint32_t stgoff = stg * 30720;
        CPW0;
        __syncthreads();
        if (kt + 1 < NT && loader) {
            const __half* s = srcb + (kt + 1) * 32;
            const uint32_t d2 = dstb + (stg ^ 1) * 30720;
            #pragma unroll
            for (int i = 0; i < 8; i++)
                CP16(d2 + i*1280, s + (size_t)(16*i) * K);
        }
        CPC;

        #pragma unroll
        for (int ks = 0; ks < 2; ks++) {
            uint32_t ah[4][4], bh[4][2];
            #pragma unroll
            for (int mb = 0; mb < 4; mb++)
                LDSM4(ah[mb][0], ah[mb][1], ah[mb][2], ah[mb][3],
                      aBase + stgoff + mb*1280 + ks*32);
            #pragma unroll
            for (int nbp = 0; nbp < 2; nbp++)
                LDSM4(bh[2*nbp][0], bh[2*nbp][1], bh[2*nbp+1][0], bh[2*nbp+1][1],
                      bBase + stgoff + nbp*1280 + ks*32);
            if (USE_BL) {
                uint32_t bl[4][2];
                #pragma unroll
                for (int nbp = 0; nbp < 2; nbp++)
                    LDSM4(bl[2*nbp][0], bl[2*nbp][1], bl[2*nbp+1][0], bl[2*nbp+1][1],
                          bBase + stgoff + 10240 + nbp*1280 + ks*32);
                #pragma unroll
                for (int nb = 0; nb < 4; nb++)
                    #pragma unroll
                    for (int mb = 0; mb < 4; mb++) {
                        mma_f16(cx.acc[mb][nb], ah[mb], bh[nb]);
                        mma_f16(cx.acc[mb][nb], ah[mb], bl[nb]);
                    }
            } else {
                #pragma unroll
                for (int nb = 0; nb < 4; nb++)
                    #pragma unroll
                    for (int mb = 0; mb < 4; mb++)
                        mma_f16(cx.acc[mb][nb], ah[mb], bh[nb]);
            }
        }
    }
}

// ---- WO projection GEMM: plain f32 output (2-term) --------------------------
__global__ __launch_bounds__(256) void gemm_2t(
    const __half* __restrict__ Ah_g,
    const __half* __restrict__ Bh_g, const __half* __restrict__ Bl_g,
    float* __restrict__ C, int ldc, int K)
{
    extern __shared__ uint32_t su[];
    const uint32_t sb = s2u(su);
    const int bm = blockIdx.y * 128, bn = blockIdx.x * 128;
    GemmCtx cx;
    gemm_mainloop<true>(Ah_g, Bh_g, Bl_g, K, bm, bn, su, sb, cx);

    #pragma unroll
    for (int mb = 0; mb < 4; mb++) {
        int r0 = bm + cx.wm + mb * 16 + cx.g;
        #pragma unroll
        for (int nb = 0; nb < 4; nb++) {
            int ccn = bn + cx.wn + nb * 8 + 2 * cx.t;
            *(float2*)(C + (size_t)r0 * ldc + ccn)       = make_float2(cx.acc[mb][nb][0], cx.acc[mb][nb][1]);
            *(float2*)(C + (size_t)(r0 + 8) * ldc + ccn) = make_float2(cx.acc[mb][nb][2], cx.acc[mb][nb][3]);
        }
    }
}

// ---- fused QKV GEMM: 2-term Q cols / 1-term K,V cols; fused epilogue --------
__global__ __launch_bounds__(256) void gemm_qkv(
    const __half* __restrict__ Ah_g,
    const __half* __restrict__ Bh_g, const __half* __restrict__ Bl_g,
    __half* __restrict__ Qh, __half* __restrict__ Kh, __half* __restrict__ Vt)
{
    extern __shared__ uint32_t su[];
    const uint32_t sb = s2u(su);
    const int tid = threadIdx.x;
    const int bm = blockIdx.y * 128, bn = blockIdx.x * 128;
    GemmCtx cx;
    if (bn < 2048)
        gemm_mainloop<true>(Ah_g, Bh_g, Bl_g, D_, bm, bn, su, sb, cx);
    else
        gemm_mainloop<false>(Ah_g, Bh_g, Bl_g, D_, bm, bn, su, sb, cx);

    float* st = (float*)su;
    __syncthreads();
    #pragma unroll
    for (int mb = 0; mb < 4; mb++) {
        int r0 = cx.wm + mb * 16 + cx.g;
        #pragma unroll
        for (int nb = 0; nb < 4; nb++) {
            int ccn = cx.wn + nb * 8 + 2 * cx.t;
            *(float2*)(st + r0 * TP + ccn)       = make_float2(cx.acc[mb][nb][0], cx.acc[mb][nb][1]);
            *(float2*)(st + (r0 + 8) * TP + ccn) = make_float2(cx.acc[mb][nb][2], cx.acc[mb][nb][3]);
        }
    }
    __syncthreads();

    if (bn < 2048) {
        const int hh = bn >> 7;
        const float scale = 0.08838834764831845f;
        for (int p = tid; p < 8192; p += 256) {
            int r = p >> 6, j = p & 63;
            int m = bm + r, tpos = m & (T_ - 1);
            float inv = powf(10000.0f, -((float)(2 * j) / 128.0f));
            float s, c;
            sincosf((float)tpos * inv, &s, &c);
            float x1 = st[r * TP + j], x2 = st[r * TP + j + 64];
            __half* dst = Qh + (size_t)m * D_ + hh * HD_;
            dst[j]      = __float2half_rn((x1 * c - x2 * s) * scale);
            dst[j + 64] = __float2half_rn((x2 * c + x1 * s) * scale);
        }
    } else if (bn < 2560) {
        const int gg = (bn - 2048) >> 7;
        for (int p = tid; p < 8192; p += 256) {
            int r = p >> 6, j = p & 63;
            int m = bm + r, tpos = m & (T_ - 1);
            float inv = powf(10000.0f, -((float)(2 * j) / 128.0f));
            float s, c;
            sincosf((float)tpos * inv, &s, &c);
            float x1 = st[r * TP + j], x2 = st[r * TP + j + 64];
            __half* dst = Kh + (size_t)m * KVD_ + gg * HD_;
            dst[j]      = __float2half_rn(x1 * c - x2 * s);
            dst[j + 64] = __float2half_rn(x2 * c + x1 * s);
        }
    } else {
        const int d0 = bn - 2560;
        const int bb = bm >> 11;
        const int t0 = bm & (T_ - 1);
        for (int p = tid; p < 16384; p += 256) {
            int dl = p >> 7, tl = p & 127;
            float v = st[tl * TP + dl];
            Vt[(size_t)(bb * KVD_ + d0 + dl) * T_ + t0 + tl] = __float2half_rn(v);
        }
    }
}

// ============================================================================
// flash attention: KV tile 128 (round-14 proven config).
// ============================================================================
#define AP 68
#define QH_OFF 0
#define KH_OFF (64*AP)
#define VH_OFF (192*AP)
#define PH_OFF (320*AP)
#define ST_OFF (384*AP)
#define FA_SMEM_BYTES ((ST_OFF + 64*3 + 4*64*2) * 4)   // ~107 KB

__global__ __launch_bounds__(256) void flash_attn_h1(
    const __half* __restrict__ Qh_g,
    const __half* __restrict__ Kh_g,
    const __half* __restrict__ Vh_g,
    __half* __restrict__ Oh_g)
{
    extern __shared__ uint32_t su[];
    const uint32_t sb = s2u(su);
    uint32_t* Ph = su + PH_OFF;
    float* m_s  = (float*)(su + ST_OFF);
    float* l_s  = m_s + 64;
    float* rs_s = l_s + 64;
    float* pmax = rs_s + 64;
    float* psum = pmax + 4*64;

    const int tid = threadIdx.x, lane = tid & 31, w = tid >> 5;
    const int qt = blockIdx.x, h = blockIdx.y, b = blockIdx.z;
    const int gq = h >> 2;
    const int q0 = qt * 64;
    const int wm = (w & 1) * 32;
    const int wn = (w >> 1) * 32;
    const int g = lane >> 2, t = lane & 3;

    const int vr = tid >> 4, vc = tid & 15;

    auto issueK = [&](int s0k) {
        const __half* src = Kh_g + (size_t)(b*T_ + s0k + vr) * KVD_ + gq*HD_ + vc*8;
        uint32_t dst = sb + (uint32_t)KH_OFF*4 + vr*272 + vc*16;
        #pragma unroll
        for (int i = 0; i < 8; i++)
            CP16(dst + i*16*272, src + (size_t)(16*i) * KVD_);
    };
    auto issueV = [&](int s0v) {
        const __half* src = Vh_g + ((size_t)(b*KV_ + gq)*HD_ + vr) * T_ + s0v + vc*8;
        uint32_t dst = sb + (uint32_t)VH_OFF*4 + vr*272 + vc*16;
        #pragma unroll
        for (int i = 0; i < 8; i++)
            CP16(dst + i*16*272, src + (size_t)(16*i) * T_);
    };

    {
        const __half* src = Qh_g + (size_t)(b*T_ + q0 + vr) * D_ + h*HD_ + vc*8;
        uint32_t dst = sb + (uint32_t)QH_OFF*4 + vr*272 + vc*16;
        #pragma unroll
        for (int i = 0; i < 4; i++)
            CP16(dst + i*16*272, src + (size_t)(16*i) * D_);
        issueK(0);
    }
    CPC;
    issueV(0);
    CPC;

    if (tid < 64) { m_s[tid] = -INFINITY; l_s[tid] = 0.f; }

    float acc[2][4][4];
    #pragma unroll
    for (int mb = 0; mb < 2; mb++)
        #pragma unroll
        for (int nb = 0; nb < 4; nb++)
            #pragma unroll
            for (int i = 0; i < 4; i++) acc[mb][nb][i] = 0.f;

    const int arow = wm + ((lane >> 3) & 1) * 8 + (lane & 7);
    const uint32_t aBase = sb + arow * 272 + (lane >> 4) * 16;
    const int brow = wn + (lane >> 4) * 8 + (lane & 7);
    const uint32_t bBase = sb + brow * 272 + ((lane >> 3) & 1) * 16;

    for (int it = 0; it < 16; it++) {
        CPW1;
        __syncthreads();

        float sfr[2][4][4];
        #pragma unroll
        for (int mb = 0; mb < 2; mb++)
            #pragma unroll
            for (int nb = 0; nb < 4; nb++)
                #pragma unroll
                for (int i = 0; i < 4; i++) sfr[mb][nb][i] = 0.f;

        #pragma unroll
        for (int k16 = 0; k16 < 8; k16++) {
            uint32_t ah[2][4], bh[4][2];
            #pragma unroll
            for (int mb = 0; mb < 2; mb++)
                LDSM4(ah[mb][0], ah[mb][1], ah[mb][2], ah[mb][3],
                      aBase + QH_OFF*4 + mb*16*272 + k16*32);
            #pragma unroll
            for (int nbp = 0; nbp < 2; nbp++)
                LDSM4(bh[2*nbp][0], bh[2*nbp][1], bh[2*nbp+1][0], bh[2*nbp+1][1],
                      bBase + KH_OFF*4 + nbp*16*272 + k16*32);
            #pragma unroll
            for (int nb = 0; nb < 4; nb++)
                #pragma unroll
                for (int mb = 0; mb < 2; mb++)
                    mma_f16(sfr[mb][nb], ah[mb], bh[nb]);
        }

        #pragma unroll
        for (int mb = 0; mb < 2; mb++) {
            float m0 = -INFINITY, m1 = -INFINITY;
            #pragma unroll
            for (int nb = 0; nb < 4; nb++) {
                m0 = fmaxf(m0, fmaxf(sfr[mb][nb][0], sfr[mb][nb][1]));
                m1 = fmaxf(m1, fmaxf(sfr[mb][nb][2], sfr[mb][nb][3]));
            }
            m0 = fmaxf(m0, __shfl_xor_sync(0xffffffffu, m0, 1));
            m0 = fmaxf(m0, __shfl_xor_sync(0xffffffffu, m0, 2));
            m1 = fmaxf(m1, __shfl_xor_sync(0xffffffffu, m1, 1));
            m1 = fmaxf(m1, __shfl_xor_sync(0xffffffffu, m1, 2));
            if (t == 0) {
                pmax[(w>>1)*64 + wm + mb*16 + g    ] = m0;
                pmax[(w>>1)*64 + wm + mb*16 + g + 8] = m1;
            }
        }
        __syncthreads();

        if (it + 1 < 16) issueK((it + 1) * 128);
        CPC;

        if (tid < 64) {
            int r = tid;
            float mt = fmaxf(fmaxf(pmax[r], pmax[64+r]), fmaxf(pmax[128+r], pmax[192+r]));
            float m_old = m_s[r];
            float m_new = fmaxf(m_old, mt);
            float rs = __expf(m_old - m_new);
            rs_s[r] = rs; m_s[r] = m_new; l_s[r] *= rs;
        }
        __syncthreads();

        float ps[2][2] = {{0.f,0.f},{0.f,0.f}};
        #pragma unroll
        for (int mb = 0; mb < 2; mb++) {
            int row0 = wm + mb*16 + g;
            float m0 = m_s[row0], m1 = m_s[row0 + 8];
            #pragma unroll
            for (int nb = 0; nb < 4; nb++) {
                int pp = (wn >> 1) + nb*4 + t;
                float p0 = __expf(sfr[mb][nb][0] - m0);
                float p1 = __expf(sfr[mb][nb][1] - m0);
                float p2 = __expf(sfr[mb][nb][2] - m1);
                float p3 = __expf(sfr[mb][nb][3] - m1);
                ps[mb][0] += p0 + p1;
                ps[mb][1] += p2 + p3;
                Ph[row0*AP + pp]     = cvth(p0, p1);
                Ph[(row0+8)*AP + pp] = cvth(p2, p3);
            }
            ps[mb][0] += __shfl_xor_sync(0xffffffffu, ps[mb][0], 1);
            ps[mb][0] += __shfl_xor_sync(0xffffffffu, ps[mb][0], 2);
            ps[mb][1] += __shfl_xor_sync(0xffffffffu, ps[mb][1], 1);
            ps[mb][1] += __shfl_xor_sync(0xffffffffu, ps[mb][1], 2);
            if (t == 0) {
                psum[(w>>1)*64 + wm + mb*16 + g    ] = ps[mb][0];
                psum[(w>>1)*64 + wm + mb*16 + g + 8] = ps[mb][1];
            }
        }
        #pragma unroll
        for (int mb = 0; mb < 2; mb++) {
            int row0 = wm + mb*16 + g;
            float r0 = rs_s[row0], r1 = rs_s[row0 + 8];
            #pragma unroll
            for (int nb = 0; nb < 4; nb++) {
                acc[mb][nb][0] *= r0; acc[mb][nb][1] *= r0;
                acc[mb][nb][2] *= r1; acc[mb][nb][3] *= r1;
            }
        }
        if (it < 15) { CPW1; } else { CPW0; }
        __syncthreads();
        if (tid < 64)
            l_s[tid] += psum[tid] + psum[64+tid] + psum[128+tid] + psum[192+tid];

        #pragma unroll
        for (int k16 = 0; k16 < 8; k16++) {
            uint32_t ah[2][4], bh[4][2];
            #pragma unroll
            for (int mb = 0; mb < 2; mb++)
                LDSM4(ah[mb][0], ah[mb][1], ah[mb][2], ah[mb][3],
                      aBase + PH_OFF*4 + mb*16*272 + k16*32);
            #pragma unroll
            for (int nbp = 0; nbp < 2; nbp++)
                LDSM4(bh[2*nbp][0], bh[2*nbp][1], bh[2*nbp+1][0], bh[2*nbp+1][1],
                      bBase + VH_OFF*4 + nbp*16*272 + k16*32);
            #pragma unroll
            for (int nb = 0; nb < 4; nb++)
                #pragma unroll
                for (int mb = 0; mb < 2; mb++)
                    mma_f16(acc[mb][nb], ah[mb], bh[nb]);
        }
        __syncthreads();

        if (it + 1 < 16) issueV((it + 1) * 128);
        CPC;
    }

    #pragma unroll
    for (int mb = 0; mb < 2; mb++) {
        int row0 = wm + mb*16 + g;
        float inv0 = 1.0f / l_s[row0];
        float inv1 = 1.0f / l_s[row0 + 8];
        #pragma unroll
        for (int nb = 0; nb < 4; nb++) {
            int col = h*HD_ + wn + nb*8 + 2*t;
            size_t o0 = (size_t)(b*T_ + q0 + row0) * D_ + col;
            size_t o1 = (size_t)(b*T_ + q0 + row0 + 8) * D_ + col;
            *(uint32_t*)(Oh_g + o0) = cvth(acc[mb][nb][0]*inv0, acc[mb][nb][1]*inv0);
            *(uint32_t*)(Oh_g + o1) = cvth(acc[mb][nb][2]*inv1, acc[mb][nb][3]*inv1);
        }
    }
}

// ---------------- launch ------------------------------------------------------
extern "C" void kernel_launch(void* const* d_in, const int* in_sizes, int n_in,
                              void* d_out, int out_size)
{
    const float* x  = (const float*)d_in[0];
    const float* wq = (const float*)d_in[1];
    const float* wk = (const float*)d_in[2];
    const float* wv = (const float*)d_in[3];
    const float* wo = (const float*)d_in[4];
    float* out = (float*)d_out;

    __half *pXh, *pW3h, *pW3l, *pWoh, *pWol;
    __half *pQh, *pKh, *pVth, *pOh;
    cudaGetSymbolAddress((void**)&pXh, g_Xh);
    cudaGetSymbolAddress((void**)&pW3h, g_W3h); cudaGetSymbolAddress((void**)&pW3l, g_W3l);
    cudaGetSymbolAddress((void**)&pWoh, g_Woh); cudaGetSymbolAddress((void**)&pWol, g_Wol);
    cudaGetSymbolAddress((void**)&pQh, g_Qh);
    cudaGetSymbolAddress((void**)&pKh, g_Kh2);
    cudaGetSymbolAddress((void**)&pVth, g_Vth);
    cudaGetSymbolAddress((void**)&pOh, g_Oh);

    cudaFuncSetAttribute(gemm_2t,  cudaFuncAttributeMaxDynamicSharedMemorySize, G2_BYTES);
    cudaFuncSetAttribute(gemm_qkv, cudaFuncAttributeMaxDynamicSharedMemorySize, G2_BYTES);
    cudaFuncSetAttribute(flash_attn_h1, cudaFuncAttributeMaxDynamicSharedMemorySize, FA_SMEM_BYTES);

    split_all<<<SPLIT_TOTAL/256, 256>>>(x, wq, wk, wv, wo,
                                        pXh, pW3h, pW3l, pWoh, pWol);

    gemm_qkv<<<dim3(NQKV/128, M_/128), 256, G2_BYTES>>>(pXh, pW3h, pW3l, pQh, pKh, pVth);

    flash_attn_h1<<<dim3(T_/64, H_, B_), 256, FA_SMEM_BYTES>>>(pQh, pKh, pVth, pOh);

    gemm_2t<<<dim3(D_/128, M_/128), 256, G2_BYTES>>>(pOh, pWoh, pWol, out, D_, D_);
}